// round 4
// baseline (speedup 1.0000x reference)
#include <cuda_runtime.h>

#define PATHS 4096
#define LPATH 8
#define DIM   256
#define HID   256
#define GATE  1024           // 4*HID
#define M1    (PATHS*LPATH)  // 32768
#define NODE  100000

// ---- scratch (static device globals; no allocation at runtime) ----
__device__ float g_X[(size_t)M1 * GATE];      // precomputed input projections (+bias)
__device__ float g_gates[(size_t)PATHS * GATE];
__device__ float g_h[(size_t)PATHS * HID];
__device__ float g_c[(size_t)PATHS * HID];
__device__ float g_m[PATHS];
__device__ float g_a[PATHS];
__device__ float g_part[32 * HID];
__device__ int   g_is64;                      // index dtype flag (1 = int64, 0 = int32)

// ============================================================================
// Index-dtype probe: the reference emits int64 indices but the harness dtype
// set is {float32, int32, bfloat16}, so 'paths' may arrive as int32. For
// little-endian int64 values in [0, NODE) every odd 32-bit word is zero; for
// uniform int32 indices that is (practically) never true across 32 elements.
// One thread, deterministic, graph-capturable.
// ============================================================================
__global__ void detect_idx_kernel(const void* __restrict__ paths_raw)
{
    const int* a = (const int*)paths_raw;
    int ok64 = 1;
#pragma unroll
    for (int i = 0; i < 64; i += 2) {
        if (a[i + 1] != 0) ok64 = 0;
    }
    g_is64 = ok64;
}

__device__ __forceinline__ long long load_idx(const void* buf, int m)
{
    if (g_is64) return ((const long long*)buf)[m];
    return (long long)((const int*)buf)[m];
}

// ============================================================================
// SGEMM-NT: C[m][n] = dot(Arow_m, Wrow_n) (+ bias / + per-row addend)
//   step < 0 : gather mode.  Arow_m = embedding[paths[m]], C = g_X,
//              out += b1[n] + b2[n]
//   step >= 0: recurrent mode. Arow_m = g_h[m], C = g_gates,
//              out += g_X[(m*LPATH + step)*GATE + n]
// Tiles: BM=BN=128, BK=16, 256 threads, 8x8 per thread.
// ============================================================================
__global__ void __launch_bounds__(256, 2)
sgemm_nt(const float* __restrict__ emb, const void* __restrict__ gidx,
         const float* __restrict__ W,
         const float* __restrict__ b1, const float* __restrict__ b2,
         int step)
{
    __shared__ __align__(16) float As[16][132];
    __shared__ __align__(16) float Ws[16][132];

    const int tid  = threadIdx.x;
    const int bx   = blockIdx.x;   // N tile (0..7)
    const int by   = blockIdx.y;   // M tile
    const int lrow = tid >> 1;          // 0..127
    const int lcol = (tid & 1) << 3;    // 0 or 8

    const float* arow;
    if (step < 0) {
        arow = emb + (size_t)load_idx(gidx, by * 128 + lrow) * DIM;
    } else {
        arow = g_h + (size_t)(by * 128 + lrow) * HID;
    }
    const float* wrow = W + (size_t)(bx * 128 + lrow) * DIM;

    const int tx = tid & 15;   // N micro-tile
    const int ty = tid >> 4;   // M micro-tile

    float acc[8][8];
#pragma unroll
    for (int i = 0; i < 8; i++)
#pragma unroll
        for (int j = 0; j < 8; j++) acc[i][j] = 0.f;

    for (int k0 = 0; k0 < DIM; k0 += 16) {
        float4 a0 = *(const float4*)(arow + k0 + lcol);
        float4 a1 = *(const float4*)(arow + k0 + lcol + 4);
        float4 w0 = *(const float4*)(wrow + k0 + lcol);
        float4 w1 = *(const float4*)(wrow + k0 + lcol + 4);

        __syncthreads();  // previous iteration's reads done before overwrite
        As[lcol + 0][lrow] = a0.x; As[lcol + 1][lrow] = a0.y;
        As[lcol + 2][lrow] = a0.z; As[lcol + 3][lrow] = a0.w;
        As[lcol + 4][lrow] = a1.x; As[lcol + 5][lrow] = a1.y;
        As[lcol + 6][lrow] = a1.z; As[lcol + 7][lrow] = a1.w;
        Ws[lcol + 0][lrow] = w0.x; Ws[lcol + 1][lrow] = w0.y;
        Ws[lcol + 2][lrow] = w0.z; Ws[lcol + 3][lrow] = w0.w;
        Ws[lcol + 4][lrow] = w1.x; Ws[lcol + 5][lrow] = w1.y;
        Ws[lcol + 6][lrow] = w1.z; Ws[lcol + 7][lrow] = w1.w;
        __syncthreads();

#pragma unroll
        for (int kk = 0; kk < 16; kk++) {
            __align__(16) float av[8];
            __align__(16) float wv[8];
            *(float4*)(av)     = *(const float4*)&As[kk][ty * 8];
            *(float4*)(av + 4) = *(const float4*)&As[kk][ty * 8 + 4];
            *(float4*)(wv)     = *(const float4*)&Ws[kk][tx * 8];
            *(float4*)(wv + 4) = *(const float4*)&Ws[kk][tx * 8 + 4];
#pragma unroll
            for (int i = 0; i < 8; i++)
#pragma unroll
                for (int j = 0; j < 8; j++)
                    acc[i][j] += av[i] * wv[j];
        }
    }

    // epilogue
    const int cbase = bx * 128 + tx * 8;
#pragma unroll
    for (int i = 0; i < 8; i++) {
        const int r = by * 128 + ty * 8 + i;
        __align__(16) float out[8];
#pragma unroll
        for (int j = 0; j < 8; j++) out[j] = acc[i][j];

        if (step < 0) {
#pragma unroll
            for (int j = 0; j < 8; j++) out[j] += b1[cbase + j] + b2[cbase + j];
            float* crow = g_X + (size_t)r * GATE + cbase;
            *(float4*)(crow)     = make_float4(out[0], out[1], out[2], out[3]);
            *(float4*)(crow + 4) = make_float4(out[4], out[5], out[6], out[7]);
        } else {
            const float* addrow = g_X + ((size_t)r * LPATH + step) * GATE + cbase;
#pragma unroll
            for (int j = 0; j < 8; j++) out[j] += addrow[j];
            float* crow = g_gates + (size_t)r * GATE + cbase;
            *(float4*)(crow)     = make_float4(out[0], out[1], out[2], out[3]);
            *(float4*)(crow + 4) = make_float4(out[4], out[5], out[6], out[7]);
        }
    }
}

// ---- LSTM cell update: gates [P,4H] (order i,f,g,o) -> h,c [P,H] ----
__global__ void lstm_update()
{
    const int idx = blockIdx.x * blockDim.x + threadIdx.x;  // 0 .. P*H-1
    const int p = idx >> 8;
    const int j = idx & 255;
    const float* gr = g_gates + (size_t)p * GATE;
    const float ig = gr[j];
    const float fg = gr[j + 256];
    const float gg = gr[j + 512];
    const float og = gr[j + 768];
    const float si = 1.f / (1.f + expf(-ig));
    const float sf = 1.f / (1.f + expf(-fg));
    const float so = 1.f / (1.f + expf(-og));
    const float tg = tanhf(gg);
    const float c  = sf * g_c[idx] + si * tg;
    g_c[idx] = c;
    g_h[idx] = so * tanhf(c);
}

__global__ void zero_hc()
{
    const int idx = blockIdx.x * blockDim.x + threadIdx.x;
    g_h[idx] = 0.f;
    g_c[idx] = 0.f;
}

// ---- row-max over hidden dim: one warp per path ----
__global__ void rowmax()
{
    const int w    = (blockIdx.x * blockDim.x + threadIdx.x) >> 5;  // path
    const int lane = threadIdx.x & 31;
    const float* hr = g_h + (size_t)w * HID;
    float v = -1e30f;
#pragma unroll
    for (int k = lane; k < HID; k += 32) v = fmaxf(v, hr[k]);
#pragma unroll
    for (int o = 16; o > 0; o >>= 1)
        v = fmaxf(v, __shfl_xor_sync(0xffffffffu, v, o));
    if (lane == 0) g_m[w] = v;
}

// ---- softmax over 4096 path logits (single block, deterministic) ----
__global__ void softmax_paths()
{
    __shared__ float red[32];
    __shared__ float bcast;
    const int tid  = threadIdx.x;          // 0..1023
    const int lane = tid & 31, wid = tid >> 5;

    float v[4];
    float mx = -1e30f;
#pragma unroll
    for (int i = 0; i < 4; i++) {
        v[i] = g_m[tid + i * 1024];
        mx = fmaxf(mx, v[i]);
    }
#pragma unroll
    for (int o = 16; o > 0; o >>= 1)
        mx = fmaxf(mx, __shfl_xor_sync(0xffffffffu, mx, o));
    if (lane == 0) red[wid] = mx;
    __syncthreads();
    if (wid == 0) {
        float m2 = red[lane];
#pragma unroll
        for (int o = 16; o > 0; o >>= 1)
            m2 = fmaxf(m2, __shfl_xor_sync(0xffffffffu, m2, o));
        if (lane == 0) bcast = m2;
    }
    __syncthreads();
    const float MX = bcast;

    float s = 0.f;
#pragma unroll
    for (int i = 0; i < 4; i++) { v[i] = expf(v[i] - MX); s += v[i]; }
#pragma unroll
    for (int o = 16; o > 0; o >>= 1)
        s += __shfl_xor_sync(0xffffffffu, s, o);
    if (lane == 0) red[wid] = s;
    __syncthreads();
    if (wid == 0) {
        float s2 = red[lane];
#pragma unroll
        for (int o = 16; o > 0; o >>= 1)
            s2 += __shfl_xor_sync(0xffffffffu, s2, o);
        if (lane == 0) bcast = s2;
    }
    __syncthreads();
    const float inv = 1.f / bcast;
#pragma unroll
    for (int i = 0; i < 4; i++) g_a[tid + i * 1024] = v[i] * inv;
}

// ---- weighted column sum: partials per 128-path chunk (no atomics) ----
__global__ void wsum()
{
    const int col = threadIdx.x;            // 0..255
    const int p0  = blockIdx.x * 128;       // 32 blocks
    float acc = 0.f;
    for (int pp = 0; pp < 128; pp++) {
        const int p = p0 + pp;
        acc += g_h[(size_t)p * HID + col] * g_a[p];
    }
    g_part[blockIdx.x * HID + col] = acc;
}

// ---- final: reduce partials, concat dot with w_lin, sigmoid ----
__global__ void final_k(const float* __restrict__ emb,
                        const void* __restrict__ uid,
                        const void* __restrict__ iid,
                        const float* __restrict__ w_lin,
                        const float* __restrict__ b_lin,
                        float* __restrict__ out)
{
    __shared__ float red[256];
    const int j = threadIdx.x;  // 0..255
    float pe = 0.f;
#pragma unroll
    for (int b = 0; b < 32; b++) pe += g_part[b * HID + j];

    const size_t u  = (size_t)load_idx(uid, 0) * DIM;
    const size_t it = (size_t)load_idx(iid, 0) * DIM;
    float v = emb[u + j]  * w_lin[j]
            + emb[it + j] * w_lin[256 + j]
            + pe          * w_lin[512 + j];
    red[j] = v;
    __syncthreads();
#pragma unroll
    for (int s = 128; s > 0; s >>= 1) {
        if (j < s) red[j] += red[j + s];
        __syncthreads();
    }
    if (j == 0) out[0] = 1.f / (1.f + expf(-(red[0] + b_lin[0])));
}

extern "C" void kernel_launch(void* const* d_in, const int* in_sizes, int n_in,
                              void* d_out, int out_size)
{
    const float* embedding = (const float*)d_in[0];
    const float* w_ih      = (const float*)d_in[1];
    const float* w_hh      = (const float*)d_in[2];
    const float* b_ih      = (const float*)d_in[3];
    const float* b_hh      = (const float*)d_in[4];
    const float* w_lin     = (const float*)d_in[5];
    const float* b_lin     = (const float*)d_in[6];
    const void*  paths     = d_in[7];
    const void*  uid       = d_in[8];
    const void*  iid       = d_in[9];

    // 0. decide whether index inputs are int64 or int32
    detect_idx_kernel<<<1, 1>>>(paths);

    // h0 = c0 = 0 (must re-init every call for determinism)
    zero_hc<<<PATHS, 256>>>();

    // X = embedding[paths] @ w_ih^T + (b_ih + b_hh)   [32768, 1024]
    sgemm_nt<<<dim3(8, 256), 256>>>(embedding, paths, w_ih, b_ih, b_hh, -1);

    // 8 recurrent steps: gates = X[:,t] + h @ w_hh^T, then cell update
    for (int t = 0; t < LPATH; t++) {
        sgemm_nt<<<dim3(8, 32), 256>>>(embedding, paths, w_hh, b_ih, b_hh, t);
        lstm_update<<<PATHS, 256>>>();
    }

    // attention over paths + final linear/sigmoid
    rowmax<<<512, 256>>>();
    softmax_paths<<<1, 1024>>>();
    wsum<<<32, 256>>>();
    final_k<<<1, 256>>>(embedding, uid, iid, w_lin, b_lin, (float*)d_out);
}

// round 11
// speedup vs baseline: 1.1535x; 1.1535x over previous
#include <cuda_runtime.h>
#include <cuda_bf16.h>
#include <cstdint>

#define PATHS 4096
#define LPATH 8
#define DIM   256
#define HID   256
#define GATE  1024           // 4*HID
#define M1    (PATHS*LPATH)  // 32768
#define NODE  100000

// ---------------------------------------------------------------------------
// Scratch (static device globals; no runtime allocation)
// ---------------------------------------------------------------------------
__device__ float g_X[(size_t)M1 * GATE];        // input projections (+bias), fp32
__device__ float g_gates[(size_t)PATHS * GATE];
__device__ float g_h[(size_t)PATHS * HID];
__device__ float g_c[(size_t)PATHS * HID];
__device__ float g_m[PATHS];
__device__ float g_a[PATHS];
__device__ float g_part[32 * HID];
__device__ int   g_is64;

// bf16 hi/lo split operands (K-major, row pitch = 256)
__device__ __align__(256) __nv_bfloat16 g_Xhi[(size_t)M1 * DIM];
__device__ __align__(256) __nv_bfloat16 g_Xlo[(size_t)M1 * DIM];
__device__ __align__(256) __nv_bfloat16 g_Hhi[(size_t)PATHS * HID];
__device__ __align__(256) __nv_bfloat16 g_Hlo[(size_t)PATHS * HID];
__device__ __align__(256) __nv_bfloat16 g_Wihhi[(size_t)GATE * DIM];
__device__ __align__(256) __nv_bfloat16 g_Wihlo[(size_t)GATE * DIM];
__device__ __align__(256) __nv_bfloat16 g_Whhhi[(size_t)GATE * HID];
__device__ __align__(256) __nv_bfloat16 g_Whhlo[(size_t)GATE * HID];

// ---------------------------------------------------------------------------
// mma.sync / ldmatrix helpers (base-target PTX, assembles for sm_103)
// ---------------------------------------------------------------------------
__device__ __forceinline__ uint32_t smem_to_u32(const void* p) {
    uint32_t a;
    asm("{ .reg .u64 t; cvta.to.shared.u64 t, %1; cvt.u32.u64 %0, t; }"
        : "=r"(a) : "l"(p));
    return a;
}

__device__ __forceinline__ void ldmx4(uint32_t addr, uint32_t* r) {
    asm volatile("ldmatrix.sync.aligned.m8n8.x4.shared.b16 {%0,%1,%2,%3}, [%4];"
                 : "=r"(r[0]), "=r"(r[1]), "=r"(r[2]), "=r"(r[3]) : "r"(addr));
}

__device__ __forceinline__ void mma16816(float* d, const uint32_t* a,
                                         uint32_t b0, uint32_t b1) {
    asm volatile(
        "mma.sync.aligned.m16n8k16.row.col.f32.bf16.bf16.f32 "
        "{%0,%1,%2,%3}, {%4,%5,%6,%7}, {%8,%9}, {%0,%1,%2,%3};"
        : "+f"(d[0]), "+f"(d[1]), "+f"(d[2]), "+f"(d[3])
        : "r"(a[0]), "r"(a[1]), "r"(a[2]), "r"(a[3]), "r"(b0), "r"(b1));
}

// ---------------------------------------------------------------------------
// Index-dtype probe (int64 reference vs possible int32 materialization)
// ---------------------------------------------------------------------------
__global__ void detect_idx_kernel(const void* __restrict__ paths_raw)
{
    const int* a = (const int*)paths_raw;
    int ok64 = 1;
#pragma unroll
    for (int i = 0; i < 64; i += 2)
        if (a[i + 1] != 0) ok64 = 0;
    g_is64 = ok64;
}

__device__ __forceinline__ long long load_idx(const void* buf, int m)
{
    if (g_is64) return ((const long long*)buf)[m];
    return (long long)((const int*)buf)[m];
}

// ---------------------------------------------------------------------------
// Precision-split conversions
// ---------------------------------------------------------------------------
__device__ __forceinline__ void split_bf16(float x, __nv_bfloat16& hi, __nv_bfloat16& lo)
{
    hi = __float2bfloat16(x);
    lo = __float2bfloat16(x - __bfloat162float(hi));
}

__global__ void conv_w(const float* __restrict__ w_ih, const float* __restrict__ w_hh)
{
    const int idx = blockIdx.x * blockDim.x + threadIdx.x;
    if (idx < GATE * DIM) {
        split_bf16(w_ih[idx], g_Wihhi[idx], g_Wihlo[idx]);
    } else {
        const int j = idx - GATE * DIM;
        split_bf16(w_hh[j], g_Whhhi[j], g_Whhlo[j]);
    }
}

__global__ void gather_conv(const float* __restrict__ emb, const void* __restrict__ paths)
{
    const int m = blockIdx.x;                 // 0..32767
    const int c = threadIdx.x;                // 0..255
    const size_t row = (size_t)load_idx(paths, m);
    const float x = emb[row * DIM + c];
    __nv_bfloat16 hi, lo;
    split_bf16(x, hi, lo);
    g_Xhi[(size_t)m * DIM + c] = hi;
    g_Xlo[(size_t)m * DIM + c] = lo;
}

// ---------------------------------------------------------------------------
// bf16 HMMA GEMM, hi/lo split, full K=256 in smem.
// C[64 x 128] tile of A[M,256] @ B[1024,256]^T.
//   step < 0 : A = g_X{hi,lo},  C -> g_X     (+ b_ih + b_hh)
//   step >= 0: A = g_H{hi,lo},  C -> g_gates (+ g_X[:,step,:])
// 256 threads; warp (wm = wid&1, wn = wid>>1) computes 32x32.
// ---------------------------------------------------------------------------
#define PITCH 264                      // bf16 elems per smem row (528B, conflict-free)
#define SA_HI 0
#define SA_LO (SA_HI + 64 * PITCH * 2)     // 33792
#define SB_HI (SA_LO + 64 * PITCH * 2)     // 67584
#define SB_LO (SB_HI + 128 * PITCH * 2)    // 135168
#define SM_TOT (SB_LO + 128 * PITCH * 2)   // 202752

__global__ void __launch_bounds__(256, 1)
mm_mma(const float* __restrict__ b1, const float* __restrict__ b2, int step)
{
    extern __shared__ char smem[];
    const uint32_t smem_base = smem_to_u32(smem);
    const int tid  = threadIdx.x;
    const int bx   = blockIdx.x;   // N tile (0..7), 128 cols
    const int by   = blockIdx.y;   // M tile, 64 rows

    const __nv_bfloat16 *Ahi, *Alo, *Bhi, *Blo;
    if (step < 0) { Ahi = g_Xhi; Alo = g_Xlo; Bhi = g_Wihhi; Blo = g_Wihlo; }
    else          { Ahi = g_Hhi; Alo = g_Hlo; Bhi = g_Whhhi; Blo = g_Whhlo; }

    const size_t arow0 = (size_t)by * 64;
    const size_t brow0 = (size_t)bx * 128;
    const __nv_bfloat16* ash = Ahi + arow0 * DIM;
    const __nv_bfloat16* asl = Alo + arow0 * DIM;
    const __nv_bfloat16* bsh = Bhi + brow0 * DIM;
    const __nv_bfloat16* bsl = Blo + brow0 * DIM;

    // ---- stage A (64x256) and B (128x256) hi/lo into padded smem ----
    for (int c = tid; c < 64 * 32; c += 256) {            // 8 iters
        const int r = c >> 5, c8 = (c & 31) << 3;
        const size_t so = (size_t)r * DIM + c8;
        const uint32_t dl = (uint32_t)(r * PITCH + c8) * 2;
        *(uint4*)(smem + SA_HI + dl) = *(const uint4*)(ash + so);
        *(uint4*)(smem + SA_LO + dl) = *(const uint4*)(asl + so);
    }
    for (int c = tid; c < 128 * 32; c += 256) {           // 16 iters
        const int r = c >> 5, c8 = (c & 31) << 3;
        const size_t so = (size_t)r * DIM + c8;
        const uint32_t dl = (uint32_t)(r * PITCH + c8) * 2;
        *(uint4*)(smem + SB_HI + dl) = *(const uint4*)(bsh + so);
        *(uint4*)(smem + SB_LO + dl) = *(const uint4*)(bsl + so);
    }
    __syncthreads();

    // ---- warp tiling ----
    const int wid  = tid >> 5;
    const int lane = tid & 31;
    const int wm   = wid & 1;          // 2 m tiles of 32
    const int wn   = wid >> 1;         // 4 n tiles of 32
    const int m_base = wm * 32;
    const int n_base = wn * 32;
    const int lr = lane & 7;
    const int lg = lane >> 3;

    // ldmatrix base addresses (k0 = 0)
    const uint32_t aoff = (uint32_t)((m_base + (lg & 1) * 8 + lr) * PITCH + (lg >> 1) * 8) * 2;
    const uint32_t boff = (uint32_t)((n_base + (lg >> 1) * 8 + lr) * PITCH + (lg & 1) * 8) * 2;
    const uint32_t aHi = smem_base + SA_HI + aoff;
    const uint32_t aLo = smem_base + SA_LO + aoff;
    const uint32_t bHi = smem_base + SB_HI + boff;
    const uint32_t bLo = smem_base + SB_LO + boff;
    const uint32_t MT_STRIDE = 16 * PITCH * 2;   // next m16/n16 tile

    float acc[2][4][4];
#pragma unroll
    for (int i = 0; i < 2; i++)
#pragma unroll
        for (int j = 0; j < 4; j++)
#pragma unroll
            for (int d = 0; d < 4; d++) acc[i][j][d] = 0.f;

#pragma unroll 2
    for (int k0 = 0; k0 < 256; k0 += 16) {
        const uint32_t ko = (uint32_t)k0 * 2;
        uint32_t ah[2][4], al[2][4], bh[2][4], bl[2][4];
        ldmx4(aHi + ko,             ah[0]);
        ldmx4(aHi + ko + MT_STRIDE, ah[1]);
        ldmx4(aLo + ko,             al[0]);
        ldmx4(aLo + ko + MT_STRIDE, al[1]);
        ldmx4(bHi + ko,             bh[0]);
        ldmx4(bHi + ko + MT_STRIDE, bh[1]);
        ldmx4(bLo + ko,             bl[0]);
        ldmx4(bLo + ko + MT_STRIDE, bl[1]);

#pragma unroll
        for (int mt = 0; mt < 2; mt++)
#pragma unroll
            for (int bt = 0; bt < 2; bt++)
#pragma unroll
                for (int sub = 0; sub < 2; sub++) {
                    const int nt = bt * 2 + sub;
                    mma16816(acc[mt][nt], ah[mt], bh[bt][2 * sub], bh[bt][2 * sub + 1]);
                    mma16816(acc[mt][nt], ah[mt], bl[bt][2 * sub], bl[bt][2 * sub + 1]);
                    mma16816(acc[mt][nt], al[mt], bh[bt][2 * sub], bh[bt][2 * sub + 1]);
                }
    }

    // ---- epilogue: fuse bias / g_X addend, write fp32 ----
    const int lq = lane >> 2;            // 0..7 (row within 8)
    const int lp = lane & 3;             // col pair
#pragma unroll
    for (int mt = 0; mt < 2; mt++) {
#pragma unroll
        for (int nt = 0; nt < 4; nt++) {
            const int gcol = bx * 128 + n_base + nt * 8 + lp * 2;
#pragma unroll
            for (int half = 0; half < 2; half++) {
                const int row = m_base + mt * 16 + lq + half * 8;
                const size_t m = arow0 + row;
                float v0 = acc[mt][nt][half * 2 + 0];
                float v1 = acc[mt][nt][half * 2 + 1];
                if (step < 0) {
                    v0 += b1[gcol]     + b2[gcol];
                    v1 += b1[gcol + 1] + b2[gcol + 1];
                    *(float2*)(g_X + m * GATE + gcol) = make_float2(v0, v1);
                } else {
                    const float2 ad = *(const float2*)(g_X + (m * LPATH + step) * GATE + gcol);
                    *(float2*)(g_gates + m * GATE + gcol) = make_float2(v0 + ad.x, v1 + ad.y);
                }
            }
        }
    }
}

// ---------------------------------------------------------------------------
// LSTM cell update: gates [P,4H] (i,f,g,o) -> h,c; also emit bf16 hi/lo h
// ---------------------------------------------------------------------------
__global__ void lstm_update()
{
    const int idx = blockIdx.x * blockDim.x + threadIdx.x;  // 0 .. P*H-1
    const int p = idx >> 8;
    const int j = idx & 255;
    const float* gr = g_gates + (size_t)p * GATE;
    const float ig = gr[j];
    const float fg = gr[j + 256];
    const float gg = gr[j + 512];
    const float og = gr[j + 768];
    const float si = 1.f / (1.f + expf(-ig));
    const float sf = 1.f / (1.f + expf(-fg));
    const float so = 1.f / (1.f + expf(-og));
    const float tg = tanhf(gg);
    const float c  = sf * g_c[idx] + si * tg;
    g_c[idx] = c;
    const float h = so * tanhf(c);
    g_h[idx] = h;
    __nv_bfloat16 hi, lo;
    split_bf16(h, hi, lo);
    g_Hhi[idx] = hi;
    g_Hlo[idx] = lo;
}

__global__ void zero_hc()
{
    const int idx = blockIdx.x * blockDim.x + threadIdx.x;
    g_h[idx] = 0.f;
    g_c[idx] = 0.f;
    g_Hhi[idx] = __float2bfloat16(0.f);
    g_Hlo[idx] = __float2bfloat16(0.f);
}

// ---- row-max over hidden dim: one warp per path ----
__global__ void rowmax()
{
    const int w    = (blockIdx.x * blockDim.x + threadIdx.x) >> 5;
    const int lane = threadIdx.x & 31;
    const float* hr = g_h + (size_t)w * HID;
    float v = -1e30f;
#pragma unroll
    for (int k = lane; k < HID; k += 32) v = fmaxf(v, hr[k]);
#pragma unroll
    for (int o = 16; o > 0; o >>= 1)
        v = fmaxf(v, __shfl_xor_sync(0xffffffffu, v, o));
    if (lane == 0) g_m[w] = v;
}

// ---- softmax over 4096 path logits (single block, deterministic) ----
__global__ void softmax_paths()
{
    __shared__ float red[32];
    __shared__ float bcast;
    const int tid  = threadIdx.x;
    const int lane = tid & 31, wid = tid >> 5;

    float v[4];
    float mx = -1e30f;
#pragma unroll
    for (int i = 0; i < 4; i++) {
        v[i] = g_m[tid + i * 1024];
        mx = fmaxf(mx, v[i]);
    }
#pragma unroll
    for (int o = 16; o > 0; o >>= 1)
        mx = fmaxf(mx, __shfl_xor_sync(0xffffffffu, mx, o));
    if (lane == 0) red[wid] = mx;
    __syncthreads();
    if (wid == 0) {
        float m2 = red[lane];
#pragma unroll
        for (int o = 16; o > 0; o >>= 1)
            m2 = fmaxf(m2, __shfl_xor_sync(0xffffffffu, m2, o));
        if (lane == 0) bcast = m2;
    }
    __syncthreads();
    const float MX = bcast;

    float s = 0.f;
#pragma unroll
    for (int i = 0; i < 4; i++) { v[i] = expf(v[i] - MX); s += v[i]; }
#pragma unroll
    for (int o = 16; o > 0; o >>= 1)
        s += __shfl_xor_sync(0xffffffffu, s, o);
    if (lane == 0) red[wid] = s;
    __syncthreads();
    if (wid == 0) {
        float s2 = red[lane];
#pragma unroll
        for (int o = 16; o > 0; o >>= 1)
            s2 += __shfl_xor_sync(0xffffffffu, s2, o);
        if (lane == 0) bcast = s2;
    }
    __syncthreads();
    const float inv = 1.f / bcast;
#pragma unroll
    for (int i = 0; i < 4; i++) g_a[tid + i * 1024] = v[i] * inv;
}

// ---- weighted column sum: partials per 128-path chunk (no atomics) ----
__global__ void wsum()
{
    const int col = threadIdx.x;
    const int p0  = blockIdx.x * 128;
    float acc = 0.f;
    for (int pp = 0; pp < 128; pp++) {
        const int p = p0 + pp;
        acc += g_h[(size_t)p * HID + col] * g_a[p];
    }
    g_part[blockIdx.x * HID + col] = acc;
}

// ---- final: reduce partials, concat dot with w_lin, sigmoid ----
__global__ void final_k(const float* __restrict__ emb,
                        const void* __restrict__ uid,
                        const void* __restrict__ iid,
                        const float* __restrict__ w_lin,
                        const float* __restrict__ b_lin,
                        float* __restrict__ out)
{
    __shared__ float red[256];
    const int j = threadIdx.x;
    float pe = 0.f;
#pragma unroll
    for (int b = 0; b < 32; b++) pe += g_part[b * HID + j];

    const size_t u  = (size_t)load_idx(uid, 0) * DIM;
    const size_t it = (size_t)load_idx(iid, 0) * DIM;
    float v = emb[u + j]  * w_lin[j]
            + emb[it + j] * w_lin[256 + j]
            + pe          * w_lin[512 + j];
    red[j] = v;
    __syncthreads();
#pragma unroll
    for (int s = 128; s > 0; s >>= 1) {
        if (j < s) red[j] += red[j + s];
        __syncthreads();
    }
    if (j == 0) out[0] = 1.f / (1.f + expf(-(red[0] + b_lin[0])));
}

extern "C" void kernel_launch(void* const* d_in, const int* in_sizes, int n_in,
                              void* d_out, int out_size)
{
    const float* embedding = (const float*)d_in[0];
    const float* w_ih      = (const float*)d_in[1];
    const float* w_hh      = (const float*)d_in[2];
    const float* b_ih      = (const float*)d_in[3];
    const float* b_hh      = (const float*)d_in[4];
    const float* w_lin     = (const float*)d_in[5];
    const float* b_lin     = (const float*)d_in[6];
    const void*  paths     = d_in[7];
    const void*  uid       = d_in[8];
    const void*  iid       = d_in[9];

    cudaFuncSetAttribute(mm_mma, cudaFuncAttributeMaxDynamicSharedMemorySize, SM_TOT);

    detect_idx_kernel<<<1, 1>>>(paths);
    zero_hc<<<PATHS, 256>>>();
    conv_w<<<2 * GATE * DIM / 256, 256>>>(w_ih, w_hh);
    gather_conv<<<M1, 256>>>(embedding, paths);

    // X = embedding[paths] @ w_ih^T + (b_ih + b_hh)   [32768, 1024]
    mm_mma<<<dim3(8, M1 / 64), 256, SM_TOT>>>(b_ih, b_hh, -1);

    // 8 recurrent steps: gates = X[:,t] + h @ w_hh^T, then cell update
    for (int t = 0; t < LPATH; t++) {
        mm_mma<<<dim3(8, PATHS / 64), 256, SM_TOT>>>(b_ih, b_hh, t);
        lstm_update<<<PATHS, 256>>>();
    }

    // attention over paths + final linear/sigmoid
    rowmax<<<512, 256>>>();
    softmax_paths<<<1, 1024>>>();
    wsum<<<32, 256>>>();
    final_k<<<1, 256>>>(embedding, uid, iid, w_lin, b_lin, (float*)d_out);
}

// round 12
// speedup vs baseline: 1.6329x; 1.4156x over previous
#include <cuda_runtime.h>
#include <cuda_bf16.h>
#include <cstdint>

#define PATHS 4096
#define LPATH 8
#define DIM   256
#define HID   256
#define GATE  1024           // 4*HID
#define M1    (PATHS*LPATH)  // 32768
#define NODE  100000

// ---------------------------------------------------------------------------
// Scratch (static device globals; no runtime allocation)
// ---------------------------------------------------------------------------
__device__ float g_X[(size_t)M1 * GATE];        // input projections (+bias), fp32,
                                                // columns in PERMUTED gate order 4*unit+gate
__device__ float g_h[(size_t)PATHS * HID];
__device__ float g_c[(size_t)PATHS * HID];
__device__ float g_m[PATHS];
__device__ float g_a[PATHS];
__device__ float g_part[32 * HID];
__device__ float g_bias[GATE];                  // (b_ih + b_hh), permuted
__device__ int   g_is64;

// bf16 hi/lo split operands (K-major, row pitch = 256)
// Weight rows PERMUTED: new row = 4*unit + gate  (gate: 0=i,1=f,2=g,3=o)
__device__ __align__(256) __nv_bfloat16 g_Xhi[(size_t)M1 * DIM];
__device__ __align__(256) __nv_bfloat16 g_Xlo[(size_t)M1 * DIM];
__device__ __align__(256) __nv_bfloat16 g_Hhi[(size_t)PATHS * HID];
__device__ __align__(256) __nv_bfloat16 g_Hlo[(size_t)PATHS * HID];
__device__ __align__(256) __nv_bfloat16 g_Wihhi[(size_t)GATE * DIM];
__device__ __align__(256) __nv_bfloat16 g_Wihlo[(size_t)GATE * DIM];
__device__ __align__(256) __nv_bfloat16 g_Whhhi[(size_t)GATE * HID];
__device__ __align__(256) __nv_bfloat16 g_Whhlo[(size_t)GATE * HID];

// ---------------------------------------------------------------------------
// PTX helpers (base-target, assembles for family-generic sm_103)
// ---------------------------------------------------------------------------
__device__ __forceinline__ uint32_t smem_to_u32(const void* p) {
    uint32_t a;
    asm("{ .reg .u64 t; cvta.to.shared.u64 t, %1; cvt.u32.u64 %0, t; }"
        : "=r"(a) : "l"(p));
    return a;
}

__device__ __forceinline__ void ldmx4(uint32_t addr, uint32_t* r) {
    asm volatile("ldmatrix.sync.aligned.m8n8.x4.shared.b16 {%0,%1,%2,%3}, [%4];"
                 : "=r"(r[0]), "=r"(r[1]), "=r"(r[2]), "=r"(r[3]) : "r"(addr));
}

__device__ __forceinline__ void mma16816(float* d, const uint32_t* a,
                                         uint32_t b0, uint32_t b1) {
    asm volatile(
        "mma.sync.aligned.m16n8k16.row.col.f32.bf16.bf16.f32 "
        "{%0,%1,%2,%3}, {%4,%5,%6,%7}, {%8,%9}, {%0,%1,%2,%3};"
        : "+f"(d[0]), "+f"(d[1]), "+f"(d[2]), "+f"(d[3])
        : "r"(a[0]), "r"(a[1]), "r"(a[2]), "r"(a[3]), "r"(b0), "r"(b1));
}

__device__ __forceinline__ void cpasync16(uint32_t dst, const void* src) {
    asm volatile("cp.async.cg.shared.global [%0], [%1], 16;"
                 :: "r"(dst), "l"(src) : "memory");
}
#define CP_COMMIT() asm volatile("cp.async.commit_group;" ::: "memory")
#define CP_WAIT0()  asm volatile("cp.async.wait_group 0;" ::: "memory")

// ---------------------------------------------------------------------------
// Index-dtype probe (int64 reference vs possible int32 materialization)
// ---------------------------------------------------------------------------
__global__ void detect_idx_kernel(const void* __restrict__ paths_raw)
{
    const int* a = (const int*)paths_raw;
    int ok64 = 1;
#pragma unroll
    for (int i = 0; i < 64; i += 2)
        if (a[i + 1] != 0) ok64 = 0;
    g_is64 = ok64;
}

__device__ __forceinline__ long long load_idx(const void* buf, int m)
{
    if (g_is64) return ((const long long*)buf)[m];
    return (long long)((const int*)buf)[m];
}

// ---------------------------------------------------------------------------
// Precision-split conversions
// ---------------------------------------------------------------------------
__device__ __forceinline__ void split_bf16(float x, __nv_bfloat16& hi, __nv_bfloat16& lo)
{
    hi = __float2bfloat16(x);
    lo = __float2bfloat16(x - __bfloat162float(hi));
}

// weights -> hi/lo bf16 with gate-interleave row permutation
__global__ void conv_w(const float* __restrict__ w_ih, const float* __restrict__ w_hh)
{
    const int idx = blockIdx.x * blockDim.x + threadIdx.x;  // 0 .. 2*262144-1
    const int half = idx >= GATE * DIM;
    const int j    = half ? idx - GATE * DIM : idx;
    const int r    = j >> 8;                 // original row
    const int c    = j & 255;
    const int newr = ((r & 255) << 2) | (r >> 8);   // 4*unit + gate
    const int dst  = (newr << 8) | c;
    if (!half) split_bf16(w_ih[j], g_Wihhi[dst], g_Wihlo[dst]);
    else       split_bf16(w_hh[j], g_Whhhi[dst], g_Whhlo[dst]);
}

__global__ void bias_perm(const float* __restrict__ b_ih, const float* __restrict__ b_hh)
{
    const int r = blockIdx.x * blockDim.x + threadIdx.x;   // 0..1023 original
    const int newr = ((r & 255) << 2) | (r >> 8);
    g_bias[newr] = b_ih[r] + b_hh[r];
}

// gather embedding rows -> hi/lo bf16 (float4 per thread, 4 rows per block)
__global__ void gather_conv(const float* __restrict__ emb, const void* __restrict__ paths)
{
    const int tid = threadIdx.x;              // 256
    const int m   = blockIdx.x * 4 + (tid >> 6);
    const int c4  = (tid & 63) << 2;
    const size_t row = (size_t)load_idx(paths, m);
    const float4 x = *(const float4*)(emb + row * DIM + c4);
    __nv_bfloat16 h0, l0, h1, l1, h2, l2, h3, l3;
    split_bf16(x.x, h0, l0); split_bf16(x.y, h1, l1);
    split_bf16(x.z, h2, l2); split_bf16(x.w, h3, l3);
    const __nv_bfloat162 hA = {h0, h1}, hB = {h2, h3};
    const __nv_bfloat162 lA = {l0, l1}, lB = {l2, l3};
    __nv_bfloat162* dh = (__nv_bfloat162*)(g_Xhi + (size_t)m * DIM + c4);
    __nv_bfloat162* dl = (__nv_bfloat162*)(g_Xlo + (size_t)m * DIM + c4);
    dh[0] = hA; dh[1] = hB;
    dl[0] = lA; dl[1] = lB;
}

// ---------------------------------------------------------------------------
// Pipelined bf16 HMMA GEMM, hi/lo split, BM=128 BN=128 KC=32, 2-stage cp.async.
//   step < 0 : A = g_X{hi,lo},  epilogue: +bias -> g_X (fp32, permuted cols)
//   step >= 0: A = g_H{hi,lo},  epilogue: +g_X[:,step,:] -> fused LSTM cell
// 256 threads (8 warps, 2x4), warp tile 64x32. smem 2 stages x 40KB = 80KB.
// ---------------------------------------------------------------------------
#define PITCH_B 80                     // bytes per smem row (40 bf16)
#define MAT_SZ  (128 * PITCH_B)        // 10240 bytes per matrix
#define STG_SZ  (4 * MAT_SZ)           // 40960 per stage
#define SM_TOT  (2 * STG_SZ)           // 81920
#define OFF_AHI 0
#define OFF_ALO MAT_SZ
#define OFF_BHI (2 * MAT_SZ)
#define OFF_BLO (3 * MAT_SZ)

__device__ __forceinline__ float sigf(float x) { return 1.f / (1.f + expf(-x)); }

__global__ void __launch_bounds__(256, 2)
mm_mma(int step)
{
    extern __shared__ char smem[];
    const uint32_t sb = smem_to_u32(smem);
    const int tid  = threadIdx.x;
    const int bx   = blockIdx.x;   // N tile (0..7), 128 cols
    const int by   = blockIdx.y;   // M tile, 128 rows

    const __nv_bfloat16 *Ahi, *Alo, *Bhi, *Blo;
    if (step < 0) { Ahi = g_Xhi; Alo = g_Xlo; Bhi = g_Wihhi; Blo = g_Wihlo; }
    else          { Ahi = g_Hhi; Alo = g_Hlo; Bhi = g_Whhhi; Blo = g_Whhlo; }

    const size_t arow0 = (size_t)by * 128;
    const size_t brow0 = (size_t)bx * 128;

    // per-thread cp.async mapping: 2048 16B chunks / stage -> 8 per thread
    // i = mat(4) x row(128) x chunk(4)
    const __nv_bfloat16* srcbase[4] = {
        Ahi + arow0 * DIM, Alo + arow0 * DIM, Bhi + brow0 * DIM, Blo + brow0 * DIM };

    // ---- warp tiling ----
    const int wid  = tid >> 5;
    const int lane = tid & 31;
    const int wm   = wid & 1;          // 2 m tiles of 64
    const int wn   = wid >> 1;         // 4 n tiles of 32
    const int lr   = lane & 7;
    const int lg   = lane >> 3;

    const uint32_t aoff = (uint32_t)(wm * 64 + (lg & 1) * 8 + lr) * PITCH_B + (lg >> 1) * 16;
    const uint32_t boff = (uint32_t)(wn * 32 + (lg >> 1) * 8 + lr) * PITCH_B + (lg & 1) * 16;

    float acc[4][4][4];
#pragma unroll
    for (int i = 0; i < 4; i++)
#pragma unroll
        for (int j = 0; j < 4; j++)
#pragma unroll
            for (int d = 0; d < 4; d++) acc[i][j][d] = 0.f;

    // ---- prologue: load stage 0 (chunk 0) ----
#pragma unroll
    for (int i = 0; i < 8; i++) {
        const int li  = i * 256 + tid;
        const int mat = li >> 9;
        const int rem = li & 511;
        const int row = rem >> 2;
        const int ch  = rem & 3;
        cpasync16(sb + mat * MAT_SZ + row * PITCH_B + ch * 16,
                  srcbase[mat] + (size_t)row * DIM + ch * 8);
    }
    CP_COMMIT();

    for (int kc = 0; kc < 8; kc++) {
        CP_WAIT0();
        __syncthreads();

        if (kc + 1 < 8) {
            const int k0n = (kc + 1) * 32;
            const uint32_t stn = sb + ((kc + 1) & 1) * STG_SZ;
#pragma unroll
            for (int i = 0; i < 8; i++) {
                const int li  = i * 256 + tid;
                const int mat = li >> 9;
                const int rem = li & 511;
                const int row = rem >> 2;
                const int ch  = rem & 3;
                cpasync16(stn + mat * MAT_SZ + row * PITCH_B + ch * 16,
                          srcbase[mat] + (size_t)row * DIM + k0n + ch * 8);
            }
            CP_COMMIT();
        }

        const uint32_t st = sb + (kc & 1) * STG_SZ;
#pragma unroll
        for (int k16 = 0; k16 < 2; k16++) {
            const uint32_t ko = k16 * 32;
            uint32_t ah[4][4], al[4][4], b[2][4];
#pragma unroll
            for (int mt = 0; mt < 4; mt++) {
                ldmx4(st + OFF_AHI + aoff + ko + mt * (16 * PITCH_B), ah[mt]);
                ldmx4(st + OFF_ALO + aoff + ko + mt * (16 * PITCH_B), al[mt]);
            }
            // B hi: Ah*Bh and Al*Bh
#pragma unroll
            for (int bt = 0; bt < 2; bt++)
                ldmx4(st + OFF_BHI + boff + ko + bt * (16 * PITCH_B), b[bt]);
#pragma unroll
            for (int mt = 0; mt < 4; mt++)
#pragma unroll
                for (int bt = 0; bt < 2; bt++)
#pragma unroll
                    for (int sub = 0; sub < 2; sub++) {
                        mma16816(acc[mt][bt * 2 + sub], ah[mt], b[bt][2 * sub], b[bt][2 * sub + 1]);
                        mma16816(acc[mt][bt * 2 + sub], al[mt], b[bt][2 * sub], b[bt][2 * sub + 1]);
                    }
            // B lo: Ah*Bl (reuse b regs)
#pragma unroll
            for (int bt = 0; bt < 2; bt++)
                ldmx4(st + OFF_BLO + boff + ko + bt * (16 * PITCH_B), b[bt]);
#pragma unroll
            for (int mt = 0; mt < 4; mt++)
#pragma unroll
                for (int bt = 0; bt < 2; bt++)
#pragma unroll
                    for (int sub = 0; sub < 2; sub++)
                        mma16816(acc[mt][bt * 2 + sub], ah[mt], b[bt][2 * sub], b[bt][2 * sub + 1]);
        }
    }

    // ---- epilogue ----
    const int lq = lane >> 2;            // 0..7 row within 8
    const int lp = lane & 3;             // col pair within n8
#pragma unroll
    for (int mt = 0; mt < 4; mt++) {
#pragma unroll
        for (int nt = 0; nt < 4; nt++) {
            const int gcol = bx * 128 + wn * 32 + nt * 8 + lp * 2;
#pragma unroll
            for (int half = 0; half < 2; half++) {
                const int rloc = wm * 64 + mt * 16 + lq + half * 8;
                const size_t m = arow0 + rloc;
                float v0 = acc[mt][nt][half * 2 + 0];
                float v1 = acc[mt][nt][half * 2 + 1];
                if (step < 0) {
                    v0 += g_bias[gcol];
                    v1 += g_bias[gcol + 1];
                    *(float2*)(g_X + m * GATE + gcol) = make_float2(v0, v1);
                } else {
                    const float2 ad = *(const float2*)(g_X + (m * LPATH + step) * GATE + gcol);
                    v0 += ad.x;
                    v1 += ad.y;
                    // assemble (i,f,g,o) quad across lane pair (lp even: i,f / odd: g,o)
                    const float w0 = __shfl_xor_sync(0xffffffffu, v0, 1);
                    const float w1 = __shfl_xor_sync(0xffffffffu, v1, 1);
                    float iv, fv, gv, ov;
                    if (lp & 1) { iv = w0; fv = w1; gv = v0; ov = v1; }
                    else        { iv = v0; fv = v1; gv = w0; ov = w1; }
                    const int unit = gcol >> 2;           // same for both lanes of pair
                    const size_t idx = m * HID + unit;
                    const float cold = g_c[idx];
                    const float cnew = sigf(fv) * cold + sigf(iv) * tanhf(gv);
                    const float h    = sigf(ov) * tanhf(cnew);
                    if (lp & 1) {
                        __nv_bfloat16 hh, hl;
                        split_bf16(h, hh, hl);
                        g_Hhi[idx] = hh;
                        g_Hlo[idx] = hl;
                    } else {
                        g_c[idx] = cnew;
                        g_h[idx] = h;
                    }
                }
            }
        }
    }
}

__global__ void zero_hc()
{
    const int idx = blockIdx.x * blockDim.x + threadIdx.x;
    g_c[idx] = 0.f;
    g_Hhi[idx] = __float2bfloat16(0.f);
    g_Hlo[idx] = __float2bfloat16(0.f);
}

// ---- row-max over hidden dim: one warp per path ----
__global__ void rowmax()
{
    const int w    = (blockIdx.x * blockDim.x + threadIdx.x) >> 5;
    const int lane = threadIdx.x & 31;
    const float* hr = g_h + (size_t)w * HID;
    float v = -1e30f;
#pragma unroll
    for (int k = lane; k < HID; k += 32) v = fmaxf(v, hr[k]);
#pragma unroll
    for (int o = 16; o > 0; o >>= 1)
        v = fmaxf(v, __shfl_xor_sync(0xffffffffu, v, o));
    if (lane == 0) g_m[w] = v;
}

// ---- softmax over 4096 path logits (single block, deterministic) ----
__global__ void softmax_paths()
{
    __shared__ float red[32];
    __shared__ float bcast;
    const int tid  = threadIdx.x;
    const int lane = tid & 31, wid = tid >> 5;

    float v[4];
    float mx = -1e30f;
#pragma unroll
    for (int i = 0; i < 4; i++) {
        v[i] = g_m[tid + i * 1024];
        mx = fmaxf(mx, v[i]);
    }
#pragma unroll
    for (int o = 16; o > 0; o >>= 1)
        mx = fmaxf(mx, __shfl_xor_sync(0xffffffffu, mx, o));
    if (lane == 0) red[wid] = mx;
    __syncthreads();
    if (wid == 0) {
        float m2 = red[lane];
#pragma unroll
        for (int o = 16; o > 0; o >>= 1)
            m2 = fmaxf(m2, __shfl_xor_sync(0xffffffffu, m2, o));
        if (lane == 0) bcast = m2;
    }
    __syncthreads();
    const float MX = bcast;

    float s = 0.f;
#pragma unroll
    for (int i = 0; i < 4; i++) { v[i] = expf(v[i] - MX); s += v[i]; }
#pragma unroll
    for (int o = 16; o > 0; o >>= 1)
        s += __shfl_xor_sync(0xffffffffu, s, o);
    if (lane == 0) red[wid] = s;
    __syncthreads();
    if (wid == 0) {
        float s2 = red[lane];
#pragma unroll
        for (int o = 16; o > 0; o >>= 1)
            s2 += __shfl_xor_sync(0xffffffffu, s2, o);
        if (lane == 0) bcast = s2;
    }
    __syncthreads();
    const float inv = 1.f / bcast;
#pragma unroll
    for (int i = 0; i < 4; i++) g_a[tid + i * 1024] = v[i] * inv;
}

// ---- weighted column sum: partials per 128-path chunk (no atomics) ----
__global__ void wsum()
{
    const int col = threadIdx.x;
    const int p0  = blockIdx.x * 128;
    float acc = 0.f;
    for (int pp = 0; pp < 128; pp++) {
        const int p = p0 + pp;
        acc += g_h[(size_t)p * HID + col] * g_a[p];
    }
    g_part[blockIdx.x * HID + col] = acc;
}

// ---- final: reduce partials, concat dot with w_lin, sigmoid ----
__global__ void final_k(const float* __restrict__ emb,
                        const void* __restrict__ uid,
                        const void* __restrict__ iid,
                        const float* __restrict__ w_lin,
                        const float* __restrict__ b_lin,
                        float* __restrict__ out)
{
    __shared__ float red[256];
    const int j = threadIdx.x;
    float pe = 0.f;
#pragma unroll
    for (int b = 0; b < 32; b++) pe += g_part[b * HID + j];

    const size_t u  = (size_t)load_idx(uid, 0) * DIM;
    const size_t it = (size_t)load_idx(iid, 0) * DIM;
    float v = emb[u + j]  * w_lin[j]
            + emb[it + j] * w_lin[256 + j]
            + pe          * w_lin[512 + j];
    red[j] = v;
    __syncthreads();
#pragma unroll
    for (int s = 128; s > 0; s >>= 1) {
        if (j < s) red[j] += red[j + s];
        __syncthreads();
    }
    if (j == 0) out[0] = 1.f / (1.f + expf(-(red[0] + b_lin[0])));
}

extern "C" void kernel_launch(void* const* d_in, const int* in_sizes, int n_in,
                              void* d_out, int out_size)
{
    const float* embedding = (const float*)d_in[0];
    const float* w_ih      = (const float*)d_in[1];
    const float* w_hh      = (const float*)d_in[2];
    const float* b_ih      = (const float*)d_in[3];
    const float* b_hh      = (const float*)d_in[4];
    const float* w_lin     = (const float*)d_in[5];
    const float* b_lin     = (const float*)d_in[6];
    const void*  paths     = d_in[7];
    const void*  uid       = d_in[8];
    const void*  iid       = d_in[9];

    cudaFuncSetAttribute(mm_mma, cudaFuncAttributeMaxDynamicSharedMemorySize, SM_TOT);

    detect_idx_kernel<<<1, 1>>>(paths);
    zero_hc<<<PATHS, 256>>>();
    conv_w<<<2 * GATE * DIM / 256, 256>>>(w_ih, w_hh);
    bias_perm<<<4, 256>>>(b_ih, b_hh);
    gather_conv<<<M1 / 4, 256>>>(embedding, paths);

    // X = embedding[paths] @ w_ih^T + bias   [32768, 1024] (permuted cols)
    mm_mma<<<dim3(8, M1 / 128), 256, SM_TOT>>>(-1);

    // 8 recurrent steps: gates = X[:,t] + h @ w_hh^T, LSTM fused in epilogue
    for (int t = 0; t < LPATH; t++)
        mm_mma<<<dim3(8, PATHS / 128), 256, SM_TOT>>>(t);

    // attention over paths + final linear/sigmoid
    rowmax<<<512, 256>>>();
    softmax_paths<<<1, 1024>>>();
    wsum<<<32, 256>>>();
    final_k<<<1, 256>>>(embedding, uid, iid, w_lin, b_lin, (float*)d_out);
}